// round 14
// baseline (speedup 1.0000x reference)
#include <cuda_runtime.h>
#include <math.h>

#define KTOT 32
#define KIND 16
#define KMLP 16
#define DH   64
#define DISTMAX 1.0f
#define MAXNODES 100001
#define MAXIV 65
#define WARPS 8
#define GWARPS 8
#define FULLMASK 0xffffffffu

// ---------------- device scratch ----------------
__device__ int   g_row_ptr[MAXNODES + 2];
__device__ float g_B[MAXIV + 1];
__device__ int   g_niv;
__device__ float g_slope[MAXIV * KMLP];
__device__ float g_icept[MAXIV * KMLP];
__device__ float g_ac, g_c1, g_bc;
__device__ int   g_fast;
__device__ int   g_sink;
__device__ __align__(16) float g_gath[MAXNODES * KTOT];
// quad-interleaved: g_nodesQ[n*32 + 4*q + j] = nodes[n][q + 8*j], q in 0..7, j in 0..3
__device__ __align__(16) float g_nodesQ[MAXNODES * KTOT];

// ---------------- packed f32x2 helpers ----------------
typedef unsigned long long u64;
__device__ __forceinline__ u64 pk2(float lo, float hi) {
    u64 r; asm("mov.b64 %0,{%1,%2};" : "=l"(r) : "f"(lo), "f"(hi)); return r;
}
__device__ __forceinline__ void upk2(u64 v, float& lo, float& hi) {
    asm("mov.b64 {%0,%1},%2;" : "=f"(lo), "=f"(hi) : "l"(v));
}
__device__ __forceinline__ u64 fma2(u64 a, u64 b, u64 c) {
    u64 r; asm("fma.rn.f32x2 %0,%1,%2,%3;" : "=l"(r) : "l"(a), "l"(b), "l"(c)); return r;
}
__device__ __forceinline__ u64 mul2(u64 a, u64 b) {
    u64 r; asm("mul.rn.f32x2 %0,%1,%2;" : "=l"(r) : "l"(a), "l"(b)); return r;
}
__device__ __forceinline__ u64 add2(u64 a, u64 b) {
    u64 r; asm("add.rn.f32x2 %0,%1,%2;" : "=l"(r) : "l"(a), "l"(b)); return r;
}
__device__ __forceinline__ float ex2f(float x) {
    float r; asm("ex2.approx.f32 %0,%1;" : "=f"(r) : "f"(x)); return r;
}

// ---------------- pre-pass: int4 rowptr scan + quad transpose + PWL ----------
__global__ void pre_kernel(const float* __restrict__ w1, const float* __restrict__ b1,
                           const float* __restrict__ w2, const float* __restrict__ b2,
                           const float* __restrict__ a,  const float* __restrict__ b,
                           const float* __restrict__ nodes,
                           const int* __restrict__ recv,
                           int n_edges, int n_nodes) {
    int t = blockIdx.x * blockDim.x + threadIdx.x;
    int lane = threadIdx.x & 31;

    // rowptr via 4-edge-per-thread boundary scan (recv sorted)
    int ne4 = n_edges >> 2;
    if (t <= ne4) {
        int e0 = t * 4;
        int r0 = 0, r1 = 0, r2 = 0, r3 = 0;
        int cnt = min(4, n_edges - e0);
        if (cnt == 4) {
            int4 rv = __ldg((const int4*)recv + t);
            r0 = rv.x; r1 = rv.y; r2 = rv.z; r3 = rv.w;
        } else if (cnt > 0) {
            r0 = __ldg(&recv[e0]);
            if (cnt > 1) r1 = __ldg(&recv[e0 + 1]);
            if (cnt > 2) r2 = __ldg(&recv[e0 + 2]);
        }
        if (cnt > 0) {
            int rp = __shfl_up_sync(FULLMASK, r3, 1);
            if (lane == 0) rp = (e0 == 0) ? -1 : __ldg(&recv[e0 - 1]);
            int rr[4] = {r0, r1, r2, r3};
            int prev = rp;
            for (int i = 0; i < cnt; i++) {
                int r = rr[i], e = e0 + i;
                for (int nn = prev + 1; nn <= r; nn++) g_row_ptr[nn] = e;
                if (e == n_edges - 1)
                    for (int nn = r + 1; nn <= n_nodes; nn++) g_row_ptr[nn] = n_edges;
                prev = r;
            }
        }
    }

    // quad transpose: out quad (f_q, f_{q+8}, f_{q+16}, f_{q+24})
    if (t < n_nodes * 8) {
        int n = t >> 3, q = t & 7;
        const float* src = nodes + (size_t)n * KTOT;
        float4 o = make_float4(__ldg(src + q),      __ldg(src + q + 8),
                               __ldg(src + q + 16), __ldg(src + q + 24));
        ((float4*)g_nodesQ)[(size_t)n * 8 + q] = o;
    }
    if (blockIdx.x != 0) return;

    // ---- PWL setup (block 0) ----
    __shared__ float sw1[DH], sb1[DH], sw2[DH * KMLP], sb2[KMLP];
    __shared__ float bps[DH];
    __shared__ int   nbp;
    __shared__ float B[MAXIV + 1];
    __shared__ int   niv_s;
    int tid = threadIdx.x;
    for (int k = tid; k < DH; k += blockDim.x) { sw1[k] = w1[k]; sb1[k] = b1[k]; }
    for (int k = tid; k < DH * KMLP; k += blockDim.x) sw2[k] = w2[k];
    if (tid < KMLP) sb2[tid] = b2[tid];
    if (tid == 0) {
        float ac = fminf(fmaxf(a[0], 0.f), 1.f);
        g_ac = ac; g_c1 = 1.f - ac;
        g_bc = fabsf(b[0]);
        nbp = 0;
    }
    __syncthreads();
    if (tid < DH) {
        float w = sw1[tid], bb = sb1[tid];
        if (w != 0.f) {
            float tt = -bb / w;
            if (tt > 0.f && tt < DISTMAX) { int k = atomicAdd(&nbp, 1); bps[k] = tt; }
        }
    }
    __syncthreads();
    if (tid == 0) {
        for (int k = 1; k < nbp; k++) {
            float vv = bps[k]; int j = k - 1;
            while (j >= 0 && bps[j] > vv) { bps[j + 1] = bps[j]; j--; }
            bps[j + 1] = vv;
        }
        B[0] = 0.f;
        for (int k = 0; k < nbp; k++) B[k + 1] = bps[k];
        B[nbp + 1] = DISTMAX;
        niv_s = nbp + 1;
        g_niv = niv_s;
        g_fast = (g_bc == 2.0f && niv_s == 1) ? 1 : 0;
    }
    __syncthreads();
    int niv = niv_s;
    for (int k = tid; k <= niv; k += blockDim.x) g_B[k] = B[k];
    for (int idx = tid; idx < niv * KMLP; idx += blockDim.x) {
        int iv = idx / KMLP, k = idx % KMLP;
        float dm = 0.5f * (B[iv] + B[iv + 1]);
        float sl = 0.f, ic = 0.f;
        for (int h = 0; h < DH; h++) {
            float w = sw1[h], bb = sb1[h];
            if (w * dm + bb > 0.f) {
                float w2v = sw2[h * KMLP + k];
                sl += w * w2v;
                ic += bb * w2v;
            }
        }
        g_slope[idx] = sl;
        g_icept[idx] = ic + sb2[k];
    }
}

// one 4-edge group step for this lane's edge (quarter). vm folds tail validity.
#define GROUP(d_, p_, nsx_, nsy_, vm_) do {                 \
    u64 tA_ = fma2(nc1v, (nsx_), nraA);                     \
    u64 sqA_ = mul2(tA_, tA_);                               \
    u64 tB_ = fma2(nc1v, (nsy_), nraB);                     \
    u64 sqB_ = mul2(tB_, tB_);                               \
    float b0_ = fmaf((d_), dscale, -flcA0);                 \
    float b1_ = fmaf((d_), dscale, -flcA1);                 \
    float i0_ = (fabsf(b0_) < 0.5f) ? (vm_) : 0.f;          \
    float i1_ = (fabsf(b1_) < 0.5f) ? (vm_) : 0.f;          \
    sumA = add2(sumA, pk2(i0_, i1_));                       \
    accA = fma2(pk2(i0_ * (p_), i1_ * (p_)), sqA_, accA);   \
    float x0_ = ex2f(fmaf(sl20, (d_), ic20)) * (vm_);       \
    float x1_ = ex2f(fmaf(sl21, (d_), ic21)) * (vm_);       \
    sumB = add2(sumB, pk2(x0_, x1_));                       \
    accB = fma2(pk2(x0_ * (p_), x1_ * (p_)), sqB_, accB);   \
} while (0)

// ---------------- gather: warp = 1 node, quarter-warp = edge, feature quads --
__global__ void __launch_bounds__(GWARPS * 32, 4)
gather_kernel(const float* __restrict__ nodes, const float* __restrict__ dist,
              const float* __restrict__ pad,   const int* __restrict__ send,
              int n_nodes) {
    __shared__ float sB[MAXIV + 1];
    __shared__ float sSl[MAXIV * KMLP], sIc[MAXIV * KMLP];

    int tid = threadIdx.x;
    const int w = tid >> 5, lane = tid & 31;
    const int fast = g_fast;
    const float binw = DISTMAX / (float)KIND;
    int wid = blockIdx.x * GWARPS + w;

    if (fast) {
        int n = wid;
        if (n >= n_nodes) return;

        int start = __ldg(&g_row_ptr[n]);
        int end   = __ldg(&g_row_ptr[n + 1]);

        const float ac = g_ac, c1 = g_c1;
        const int q4 = lane >> 3;          // quarter = which edge of the group
        const int fq = lane & 7;           // feature quad (fq, fq+8, fq+16, fq+24)
        const float dscale = (float)KIND / DISTMAX;
        const float flcA0 = (float)fq + 0.5f;
        const float flcA1 = (float)fq + 8.5f;
        const float L2E = 1.4426950408889634f;
        float sl20 = __ldg(&g_slope[fq]) * L2E;
        float sl21 = __ldg(&g_slope[fq + 8]) * L2E;
        float ic20 = -fmaxf(sl20 * DISTMAX, 0.f);   // constant base (cancels in ratio)
        float ic21 = -fmaxf(sl21 * DISTMAX, 0.f);

        const char* nQ = (const char*)g_nodesQ + fq * 16;
        ulonglong2 nr = __ldg((const ulonglong2*)(nQ + (size_t)n * 128));
        u64 ac2v = pk2(ac, ac);
        u64 nraA = mul2(ac2v, nr.x);
        u64 nraB = mul2(ac2v, nr.y);
        u64 nc1v = pk2(-c1, -c1);

        u64 accA = 0ull, sumA = 0ull, accB = 0ull, sumB = 0ull;

        int deg = end - start;
        int full = deg >> 2, rem = deg & 3;

        if (full > 0) {
            int e0 = start + q4;
            float d0 = __ldg(&dist[e0]);
            float p0 = __ldg(&pad[e0]);
            int   s0 = __ldg(&send[e0]);
            ulonglong2 ns0 = __ldg((const ulonglong2*)(nQ + (size_t)s0 * 128));

            #pragma unroll 2
            for (int g = 1; g < full; g++) {
                int e1 = start + g * 4 + q4;
                float d1 = __ldg(&dist[e1]);
                float p1 = __ldg(&pad[e1]);
                int   s1 = __ldg(&send[e1]);
                GROUP(d0, p0, ns0.x, ns0.y, 1.f);
                ns0 = __ldg((const ulonglong2*)(nQ + (size_t)s1 * 128));
                d0 = d1; p0 = p1;
            }
            GROUP(d0, p0, ns0.x, ns0.y, 1.f);
        }
        if (rem) {
            int idx = start + full * 4 + q4;
            int ic  = min(idx, end - 1);
            float vm = (idx < end) ? 1.f : 0.f;
            float d0 = __ldg(&dist[ic]);
            float p0 = __ldg(&pad[ic]);
            int   s0 = __ldg(&send[ic]);
            ulonglong2 ns0 = __ldg((const ulonglong2*)(nQ + (size_t)s0 * 128));
            GROUP(d0, p0, ns0.x, ns0.y, vm);
        }

        // combine quarter-warps (disjoint edges, same feature quads)
        accA = add2(accA, __shfl_xor_sync(FULLMASK, accA, 8));
        accA = add2(accA, __shfl_xor_sync(FULLMASK, accA, 16));
        sumA = add2(sumA, __shfl_xor_sync(FULLMASK, sumA, 8));
        sumA = add2(sumA, __shfl_xor_sync(FULLMASK, sumA, 16));
        accB = add2(accB, __shfl_xor_sync(FULLMASK, accB, 8));
        accB = add2(accB, __shfl_xor_sync(FULLMASK, accB, 16));
        sumB = add2(sumB, __shfl_xor_sync(FULLMASK, sumB, 8));
        sumB = add2(sumB, __shfl_xor_sync(FULLMASK, sumB, 16));

        if (lane < 8) {
            float a0, a1, c0, c1f, b0v, b1v, sv0, sv1;
            upk2(accA, a0, a1);  upk2(sumA, c0, c1f);
            upk2(accB, b0v, b1v); upk2(sumB, sv0, sv1);
            float* go = g_gath + (size_t)n * KTOT;
            go[fq]      = __fdividef(a0, c0 + 1e-5f);
            go[fq + 8]  = __fdividef(a1, c1f + 1e-5f);
            go[16 + fq] = (sv0 > 0.f) ? __fdividef(b0v, sv0) : 0.f;
            go[24 + fq] = (sv1 > 0.f) ? __fdividef(b1v, sv1) : 0.f;
        }
        return;
    }

    // ---------------- generic fallback (any b, multi-interval PWL) ----------
    int niv = g_niv;
    for (int i = tid; i <= niv; i += blockDim.x) sB[i] = g_B[i];
    for (int i = tid; i < niv * KMLP; i += blockDim.x) { sSl[i] = g_slope[i]; sIc[i] = g_icept[i]; }
    __syncthreads();

    int n = wid;
    if (n >= n_nodes) return;
    const float ac = g_ac, c1 = g_c1, bc = g_bc;
    const float lo_b = (float)lane * binw;
    const float hi_b = lo_b + binw;
    const int mk = lane & (KMLP - 1);

    float nval = nodes[(size_t)n * KTOT + lane];
    float nra  = ac * nval;
    int start = g_row_ptr[n], end = g_row_ptr[n + 1];
    const float* nl = nodes + lane;

    float cnt = 0.f, ai = 0.f, am = 0.f, s = 0.f, m = -INFINITY;
    for (int e = start; e < end; e++) {
        float d   = __ldg(&dist[e]);
        float pp  = __ldg(&pad[e]);
        int   sid = __ldg(&send[e]);
        float nsv = __ldg(nl + (size_t)sid * KTOT);
        float t   = fmaf(-c1, nsv, nra);
        float we  = pp * powf(fabsf(t), bc);
        if ((d > lo_b) && (d < hi_b)) { cnt += 1.f; ai += we; }
        int lo = 0, hi = niv - 1;
        while (lo < hi) {
            int mid = (lo + hi + 1) >> 1;
            if (d >= sB[mid]) lo = mid; else hi = mid - 1;
        }
        float vv = fmaf(sSl[lo * KMLP + mk], d, sIc[lo * KMLP + mk]);
        float nm = fmaxf(m, vv);
        float sc = __expf(m - nm);
        float p  = __expf(vv - nm);
        s  = fmaf(s, sc, p);
        am = fmaf(am, sc, p * we);
        m  = nm;
    }
    float g;
    if (lane < KIND) g = __fdividef(ai, cnt + 1e-5f);
    else             g = (s > 0.f) ? __fdividef(am, s) : 0.f;
    g_gath[(size_t)n * KTOT + lane] = g;
}

// ---------------- epilogue: out = relu(nodes@WS + gath@WG + bg) --------------
__global__ void __launch_bounds__(WARPS * 32)
epi_kernel(const float* __restrict__ nodes, const float* __restrict__ wgs,
           const float* __restrict__ wgg,   const float* __restrict__ bgg,
           float* __restrict__ out, int n_nodes) {
    __shared__ float4 sX[WARPS][8][8];
    __shared__ float4 sG[WARPS][8][8];

    int tid = threadIdx.x;
    int w = tid >> 5, lane = tid & 31;

    float ws[KTOT], wg[KTOT];
    #pragma unroll
    for (int j = 0; j < KTOT; j++) {
        ws[j] = __ldg(&wgs[j * KTOT + lane]);
        wg[j] = __ldg(&wgg[j * KTOT + lane]);
    }
    float bgk = __ldg(&bgg[lane]);

    int wid = blockIdx.x * WARPS + w;
    int n0 = wid * 8;
    if (n0 >= n_nodes) return;

    const float4* x4 = (const float4*)nodes;
    const float4* g4 = (const float4*)g_gath;
    int lim4 = n_nodes * 8;
    {
        int i1 = lane >> 3, j1 = lane & 7;
        int idxA = n0 * 8 + lane, idxB = idxA + 32;
        float4 z = make_float4(0.f, 0.f, 0.f, 0.f);
        sX[w][i1][j1]     = (idxA < lim4) ? __ldg(&x4[idxA]) : z;
        sX[w][i1 + 4][j1] = (idxB < lim4) ? __ldg(&x4[idxB]) : z;
        sG[w][i1][j1]     = (idxA < lim4) ? __ldg(&g4[idxA]) : z;
        sG[w][i1 + 4][j1] = (idxB < lim4) ? __ldg(&g4[idxB]) : z;
    }
    __syncwarp();

    #pragma unroll
    for (int i = 0; i < 8; i++) {
        int n = n0 + i;
        if (n >= n_nodes) break;
        float o = bgk;
        #pragma unroll
        for (int j4 = 0; j4 < 8; j4++) {
            float4 xv = sX[w][i][j4];
            float4 gv = sG[w][i][j4];
            o = fmaf(xv.x, ws[j4 * 4 + 0], o);
            o = fmaf(xv.y, ws[j4 * 4 + 1], o);
            o = fmaf(xv.z, ws[j4 * 4 + 2], o);
            o = fmaf(xv.w, ws[j4 * 4 + 3], o);
            o = fmaf(gv.x, wg[j4 * 4 + 0], o);
            o = fmaf(gv.y, wg[j4 * 4 + 1], o);
            o = fmaf(gv.z, wg[j4 * 4 + 2], o);
            o = fmaf(gv.w, wg[j4 * 4 + 3], o);
        }
        out[(size_t)n * KTOT + lane] = fmaxf(o, 0.f);
    }
}

// ---------------- dummy: shifts ncu -s 5 -c 1 onto gather (launch #6) --------
__global__ void dummy_kernel() {
    if (threadIdx.x == 0 && blockIdx.x == 0) g_sink = 1;
}

// ---------------- launch ----------------
extern "C" void kernel_launch(void* const* d_in, const int* in_sizes, int n_in,
                              void* d_out, int out_size) {
    const float* nodes     = (const float*)d_in[0];
    const float* distance  = (const float*)d_in[1];
    const float* padding   = (const float*)d_in[2];
    const int*   receivers = (const int*)d_in[3];
    const int*   senders   = (const int*)d_in[4];
    const float* w1        = (const float*)d_in[5];
    const float* b1        = (const float*)d_in[6];
    const float* w2        = (const float*)d_in[7];
    const float* b2        = (const float*)d_in[8];
    const float* a         = (const float*)d_in[9];
    const float* b         = (const float*)d_in[10];
    const float* wgs       = (const float*)d_in[11];
    const float* wgg       = (const float*)d_in[12];
    const float* bgg       = (const float*)d_in[13];

    int n_nodes = in_sizes[0] / KTOT;
    int n_edges = in_sizes[1];

    int ethreads = (n_edges >> 2) + 1;
    int pwork = ethreads > n_nodes * 8 ? ethreads : n_nodes * 8;
    int pblocks = (pwork + 255) / 256;
    if (pblocks < 1) pblocks = 1;
    pre_kernel<<<pblocks, 256>>>(w1, b1, w2, b2, a, b, nodes,
                                 receivers, n_edges, n_nodes);

    int gblocks = (n_nodes + GWARPS - 1) / GWARPS;
    gather_kernel<<<gblocks, GWARPS * 32>>>(nodes, distance, padding, senders, n_nodes);

    int nwarps = (n_nodes + 7) / 8;
    int eblocks = (nwarps + WARPS - 1) / WARPS;
    epi_kernel<<<eblocks, WARPS * 32>>>(nodes, wgs, wgg, bgg, (float*)d_out, n_nodes);

    dummy_kernel<<<1, 32>>>();
}

// round 15
// speedup vs baseline: 1.1406x; 1.1406x over previous
#include <cuda_runtime.h>
#include <math.h>

#define KTOT 32
#define KIND 16
#define KMLP 16
#define DH   64
#define DISTMAX 1.0f
#define MAXNODES 100001
#define MAXIV 65
#define WARPS 8
#define GWARPS 4
#define FULLMASK 0xffffffffu

// ---------------- device scratch ----------------
__device__ int   g_row_ptr[MAXNODES + 2];
__device__ float g_B[MAXIV + 1];
__device__ int   g_niv;
__device__ float g_slope[MAXIV * KMLP];
__device__ float g_icept[MAXIV * KMLP];
__device__ float g_ac, g_c1, g_bc;
__device__ int   g_fast;
__device__ int   g_pad1 = 1;    // all edges_padding == 1 ? (sticky: same inputs every call)
__device__ __align__(16) float g_gath[MAXNODES * KTOT];
// quad-interleaved: g_nodesQ[n*32 + 4*q + j] = nodes[n][q + 8*j], q in 0..7, j in 0..3
__device__ __align__(16) float g_nodesQ[MAXNODES * KTOT];

// ---------------- packed f32x2 helpers ----------------
typedef unsigned long long u64;
__device__ __forceinline__ u64 pk2(float lo, float hi) {
    u64 r; asm("mov.b64 %0,{%1,%2};" : "=l"(r) : "f"(lo), "f"(hi)); return r;
}
__device__ __forceinline__ void upk2(u64 v, float& lo, float& hi) {
    asm("mov.b64 {%0,%1},%2;" : "=f"(lo), "=f"(hi) : "l"(v));
}
__device__ __forceinline__ u64 fma2(u64 a, u64 b, u64 c) {
    u64 r; asm("fma.rn.f32x2 %0,%1,%2,%3;" : "=l"(r) : "l"(a), "l"(b), "l"(c)); return r;
}
__device__ __forceinline__ u64 mul2(u64 a, u64 b) {
    u64 r; asm("mul.rn.f32x2 %0,%1,%2;" : "=l"(r) : "l"(a), "l"(b)); return r;
}
__device__ __forceinline__ u64 add2(u64 a, u64 b) {
    u64 r; asm("add.rn.f32x2 %0,%1,%2;" : "=l"(r) : "l"(a), "l"(b)); return r;
}
__device__ __forceinline__ float ex2f(float x) {
    float r; asm("ex2.approx.f32 %0,%1;" : "=f"(r) : "f"(x)); return r;
}

// ---------------- pre-pass: int4 rowptr scan + pad check + transpose + PWL ---
__global__ void pre_kernel(const float* __restrict__ w1, const float* __restrict__ b1,
                           const float* __restrict__ w2, const float* __restrict__ b2,
                           const float* __restrict__ a,  const float* __restrict__ b,
                           const float* __restrict__ nodes,
                           const int* __restrict__ recv, const float* __restrict__ pad,
                           int n_edges, int n_nodes) {
    int t = blockIdx.x * blockDim.x + threadIdx.x;
    int lane = threadIdx.x & 31;

    // rowptr via 4-edge-per-thread boundary scan (recv sorted) + pad==1 check
    int ne4 = n_edges >> 2;
    if (t <= ne4) {
        int e0 = t * 4;
        int r0 = 0, r1 = 0, r2 = 0, r3 = 0;
        int cnt = min(4, n_edges - e0);
        if (cnt == 4) {
            int4 rv = __ldg((const int4*)recv + t);
            r0 = rv.x; r1 = rv.y; r2 = rv.z; r3 = rv.w;
            float4 pv = __ldg((const float4*)pad + t);
            if (pv.x != 1.f || pv.y != 1.f || pv.z != 1.f || pv.w != 1.f) g_pad1 = 0;
        } else if (cnt > 0) {
            r0 = __ldg(&recv[e0]);
            if (__ldg(&pad[e0]) != 1.f) g_pad1 = 0;
            if (cnt > 1) { r1 = __ldg(&recv[e0 + 1]); if (__ldg(&pad[e0 + 1]) != 1.f) g_pad1 = 0; }
            if (cnt > 2) { r2 = __ldg(&recv[e0 + 2]); if (__ldg(&pad[e0 + 2]) != 1.f) g_pad1 = 0; }
        }
        if (cnt > 0) {
            int rp = __shfl_up_sync(FULLMASK, r3, 1);
            if (lane == 0) rp = (e0 == 0) ? -1 : __ldg(&recv[e0 - 1]);
            int rr[4] = {r0, r1, r2, r3};
            int prev = rp;
            for (int i = 0; i < cnt; i++) {
                int r = rr[i], e = e0 + i;
                for (int nn = prev + 1; nn <= r; nn++) g_row_ptr[nn] = e;
                if (e == n_edges - 1)
                    for (int nn = r + 1; nn <= n_nodes; nn++) g_row_ptr[nn] = n_edges;
                prev = r;
            }
        }
    }

    // quad transpose: out quad (f_q, f_{q+8}, f_{q+16}, f_{q+24})
    if (t < n_nodes * 8) {
        int n = t >> 3, q = t & 7;
        const float* src = nodes + (size_t)n * KTOT;
        float4 o = make_float4(__ldg(src + q),      __ldg(src + q + 8),
                               __ldg(src + q + 16), __ldg(src + q + 24));
        ((float4*)g_nodesQ)[(size_t)n * 8 + q] = o;
    }
    if (blockIdx.x != 0) return;

    // ---- PWL setup (block 0) ----
    __shared__ float sw1[DH], sb1[DH], sw2[DH * KMLP], sb2[KMLP];
    __shared__ float bps[DH];
    __shared__ int   nbp;
    __shared__ float B[MAXIV + 1];
    __shared__ int   niv_s;
    int tid = threadIdx.x;
    for (int k = tid; k < DH; k += blockDim.x) { sw1[k] = w1[k]; sb1[k] = b1[k]; }
    for (int k = tid; k < DH * KMLP; k += blockDim.x) sw2[k] = w2[k];
    if (tid < KMLP) sb2[tid] = b2[tid];
    if (tid == 0) {
        float ac = fminf(fmaxf(a[0], 0.f), 1.f);
        g_ac = ac; g_c1 = 1.f - ac;
        g_bc = fabsf(b[0]);
        nbp = 0;
    }
    __syncthreads();
    if (tid < DH) {
        float w = sw1[tid], bb = sb1[tid];
        if (w != 0.f) {
            float tt = -bb / w;
            if (tt > 0.f && tt < DISTMAX) { int k = atomicAdd(&nbp, 1); bps[k] = tt; }
        }
    }
    __syncthreads();
    if (tid == 0) {
        for (int k = 1; k < nbp; k++) {
            float vv = bps[k]; int j = k - 1;
            while (j >= 0 && bps[j] > vv) { bps[j + 1] = bps[j]; j--; }
            bps[j + 1] = vv;
        }
        B[0] = 0.f;
        for (int k = 0; k < nbp; k++) B[k + 1] = bps[k];
        B[nbp + 1] = DISTMAX;
        niv_s = nbp + 1;
        g_niv = niv_s;
        g_fast = (g_bc == 2.0f && niv_s == 1) ? 1 : 0;
    }
    __syncthreads();
    int niv = niv_s;
    for (int k = tid; k <= niv; k += blockDim.x) g_B[k] = B[k];
    for (int idx = tid; idx < niv * KMLP; idx += blockDim.x) {
        int iv = idx / KMLP, k = idx % KMLP;
        float dm = 0.5f * (B[iv] + B[iv + 1]);
        float sl = 0.f, ic = 0.f;
        for (int h = 0; h < DH; h++) {
            float w = sw1[h], bb = sb1[h];
            if (w * dm + bb > 0.f) {
                float w2v = sw2[h * KMLP + k];
                sl += w * w2v;
                ic += bb * w2v;
            }
        }
        g_slope[idx] = sl;
        g_icept[idx] = ic + sb2[k];
    }
}

// one 4-edge group step (with pad). vm folds tail validity.
#define GROUP(d_, p_, nsx_, nsy_, vm_) do {                 \
    u64 tA_ = fma2(nc1v, (nsx_), nraA);                     \
    u64 sqA_ = mul2(tA_, tA_);                               \
    u64 tB_ = fma2(nc1v, (nsy_), nraB);                     \
    u64 sqB_ = mul2(tB_, tB_);                               \
    float b0_ = fmaf((d_), dscale, -flcA0);                 \
    float b1_ = fmaf((d_), dscale, -flcA1);                 \
    float i0_ = (fabsf(b0_) < 0.5f) ? (vm_) : 0.f;          \
    float i1_ = (fabsf(b1_) < 0.5f) ? (vm_) : 0.f;          \
    sumA = add2(sumA, pk2(i0_, i1_));                       \
    accA = fma2(pk2(i0_ * (p_), i1_ * (p_)), sqA_, accA);   \
    float x0_ = ex2f(fmaf(sl20, (d_), ic20)) * (vm_);       \
    float x1_ = ex2f(fmaf(sl21, (d_), ic21)) * (vm_);       \
    sumB = add2(sumB, pk2(x0_, x1_));                       \
    accB = fma2(pk2(x0_ * (p_), x1_ * (p_)), sqB_, accB);   \
} while (0)

// pad-free variant: pad==1 verified -> weight vectors shared by sum and acc.
#define GROUP_NP(d_, nsx_, nsy_, vm_) do {                  \
    u64 tA_ = fma2(nc1v, (nsx_), nraA);                     \
    u64 sqA_ = mul2(tA_, tA_);                               \
    u64 tB_ = fma2(nc1v, (nsy_), nraB);                     \
    u64 sqB_ = mul2(tB_, tB_);                               \
    float b0_ = fmaf((d_), dscale, -flcA0);                 \
    float b1_ = fmaf((d_), dscale, -flcA1);                 \
    float i0_ = (fabsf(b0_) < 0.5f) ? (vm_) : 0.f;          \
    float i1_ = (fabsf(b1_) < 0.5f) ? (vm_) : 0.f;          \
    u64 wi_ = pk2(i0_, i1_);                                \
    sumA = add2(sumA, wi_);                                 \
    accA = fma2(wi_, sqA_, accA);                           \
    float x0_ = ex2f(fmaf(sl20, (d_), ic20)) * (vm_);       \
    float x1_ = ex2f(fmaf(sl21, (d_), ic21)) * (vm_);       \
    u64 wx_ = pk2(x0_, x1_);                                \
    sumB = add2(sumB, wx_);                                 \
    accB = fma2(wx_, sqB_, accB);                           \
} while (0)

// ---------------- gather: warp = 1 node, quarter-warp = edge, feature quads --
__global__ void __launch_bounds__(GWARPS * 32)
gather_kernel(const float* __restrict__ nodes, const float* __restrict__ dist,
              const float* __restrict__ pad,   const int* __restrict__ send,
              int n_nodes) {
    __shared__ float sB[MAXIV + 1];
    __shared__ float sSl[MAXIV * KMLP], sIc[MAXIV * KMLP];

    int tid = threadIdx.x;
    const int w = tid >> 5, lane = tid & 31;
    const int fast = g_fast;
    const float binw = DISTMAX / (float)KIND;
    int wid = blockIdx.x * GWARPS + w;

    if (fast) {
        int n = wid;
        if (n >= n_nodes) return;

        const float ac = g_ac, c1 = g_c1;
        const int q4 = lane >> 3;          // quarter = which edge of the group
        const int fq = lane & 7;           // feature quad (fq, fq+8, fq+16, fq+24)
        const float dscale = (float)KIND / DISTMAX;
        const float flcA0 = (float)fq + 0.5f;
        const float flcA1 = (float)fq + 8.5f;
        const float L2E = 1.4426950408889634f;
        float sl20 = __ldg(&g_slope[fq]) * L2E;
        float sl21 = __ldg(&g_slope[fq + 8]) * L2E;
        float ic20 = -fmaxf(sl20 * DISTMAX, 0.f);   // constant base (cancels in ratio)
        float ic21 = -fmaxf(sl21 * DISTMAX, 0.f);

        int start = __ldg(&g_row_ptr[n]);
        int end   = __ldg(&g_row_ptr[n + 1]);
        const char* nQ = (const char*)g_nodesQ + fq * 16;
        ulonglong2 nr = __ldg((const ulonglong2*)(nQ + (size_t)n * 128));
        u64 ac2v = pk2(ac, ac);
        u64 nraA = mul2(ac2v, nr.x);
        u64 nraB = mul2(ac2v, nr.y);
        u64 nc1v = pk2(-c1, -c1);

        u64 accA = 0ull, sumA = 0ull, accB = 0ull, sumB = 0ull;

        int deg = end - start;
        int full = deg >> 2, rem = deg & 3;

        if (g_pad1) {
            // ---- pad-free fast loop ----
            if (full > 0) {
                int e0 = start + q4;
                float d0 = __ldg(&dist[e0]);
                int   s0 = __ldg(&send[e0]);
                ulonglong2 ns0 = __ldg((const ulonglong2*)(nQ + (size_t)s0 * 128));

                #pragma unroll 2
                for (int g = 1; g < full; g++) {
                    int e1 = start + g * 4 + q4;
                    float d1 = __ldg(&dist[e1]);
                    int   s1 = __ldg(&send[e1]);
                    GROUP_NP(d0, ns0.x, ns0.y, 1.f);
                    ns0 = __ldg((const ulonglong2*)(nQ + (size_t)s1 * 128));
                    d0 = d1;
                }
                GROUP_NP(d0, ns0.x, ns0.y, 1.f);
            }
            if (rem) {
                int idx = start + full * 4 + q4;
                int ic  = min(idx, end - 1);
                float vm = (idx < end) ? 1.f : 0.f;
                float d0 = __ldg(&dist[ic]);
                int   s0 = __ldg(&send[ic]);
                ulonglong2 ns0 = __ldg((const ulonglong2*)(nQ + (size_t)s0 * 128));
                GROUP_NP(d0, ns0.x, ns0.y, vm);
            }
        } else {
            // ---- pad-aware loop ----
            if (full > 0) {
                int e0 = start + q4;
                float d0 = __ldg(&dist[e0]);
                float p0 = __ldg(&pad[e0]);
                int   s0 = __ldg(&send[e0]);
                ulonglong2 ns0 = __ldg((const ulonglong2*)(nQ + (size_t)s0 * 128));

                #pragma unroll 2
                for (int g = 1; g < full; g++) {
                    int e1 = start + g * 4 + q4;
                    float d1 = __ldg(&dist[e1]);
                    float p1 = __ldg(&pad[e1]);
                    int   s1 = __ldg(&send[e1]);
                    GROUP(d0, p0, ns0.x, ns0.y, 1.f);
                    ns0 = __ldg((const ulonglong2*)(nQ + (size_t)s1 * 128));
                    d0 = d1; p0 = p1;
                }
                GROUP(d0, p0, ns0.x, ns0.y, 1.f);
            }
            if (rem) {
                int idx = start + full * 4 + q4;
                int ic  = min(idx, end - 1);
                float vm = (idx < end) ? 1.f : 0.f;
                float d0 = __ldg(&dist[ic]);
                float p0 = __ldg(&pad[ic]);
                int   s0 = __ldg(&send[ic]);
                ulonglong2 ns0 = __ldg((const ulonglong2*)(nQ + (size_t)s0 * 128));
                GROUP(d0, p0, ns0.x, ns0.y, vm);
            }
        }

        // combine quarter-warps (disjoint edges, same feature quads)
        accA = add2(accA, __shfl_xor_sync(FULLMASK, accA, 8));
        accA = add2(accA, __shfl_xor_sync(FULLMASK, accA, 16));
        sumA = add2(sumA, __shfl_xor_sync(FULLMASK, sumA, 8));
        sumA = add2(sumA, __shfl_xor_sync(FULLMASK, sumA, 16));
        accB = add2(accB, __shfl_xor_sync(FULLMASK, accB, 8));
        accB = add2(accB, __shfl_xor_sync(FULLMASK, accB, 16));
        sumB = add2(sumB, __shfl_xor_sync(FULLMASK, sumB, 8));
        sumB = add2(sumB, __shfl_xor_sync(FULLMASK, sumB, 16));

        if (lane < 8) {
            float a0, a1, c0, c1f, b0v, b1v, sv0, sv1;
            upk2(accA, a0, a1);  upk2(sumA, c0, c1f);
            upk2(accB, b0v, b1v); upk2(sumB, sv0, sv1);
            float* go = g_gath + (size_t)n * KTOT;
            go[fq]      = __fdividef(a0, c0 + 1e-5f);
            go[fq + 8]  = __fdividef(a1, c1f + 1e-5f);
            go[16 + fq] = (sv0 > 0.f) ? __fdividef(b0v, sv0) : 0.f;
            go[24 + fq] = (sv1 > 0.f) ? __fdividef(b1v, sv1) : 0.f;
        }
        return;
    }

    // ---------------- generic fallback (any b, multi-interval PWL) ----------
    int niv = g_niv;
    for (int i = tid; i <= niv; i += blockDim.x) sB[i] = g_B[i];
    for (int i = tid; i < niv * KMLP; i += blockDim.x) { sSl[i] = g_slope[i]; sIc[i] = g_icept[i]; }
    __syncthreads();

    int n = wid;
    if (n >= n_nodes) return;
    const float ac = g_ac, c1 = g_c1, bc = g_bc;
    const float lo_b = (float)lane * binw;
    const float hi_b = lo_b + binw;
    const int mk = lane & (KMLP - 1);

    float nval = nodes[(size_t)n * KTOT + lane];
    float nra  = ac * nval;
    int start = g_row_ptr[n], end = g_row_ptr[n + 1];
    const float* nl = nodes + lane;

    float cnt = 0.f, ai = 0.f, am = 0.f, s = 0.f, m = -INFINITY;
    for (int e = start; e < end; e++) {
        float d   = __ldg(&dist[e]);
        float pp  = __ldg(&pad[e]);
        int   sid = __ldg(&send[e]);
        float nsv = __ldg(nl + (size_t)sid * KTOT);
        float t   = fmaf(-c1, nsv, nra);
        float we  = pp * powf(fabsf(t), bc);
        if ((d > lo_b) && (d < hi_b)) { cnt += 1.f; ai += we; }
        int lo = 0, hi = niv - 1;
        while (lo < hi) {
            int mid = (lo + hi + 1) >> 1;
            if (d >= sB[mid]) lo = mid; else hi = mid - 1;
        }
        float vv = fmaf(sSl[lo * KMLP + mk], d, sIc[lo * KMLP + mk]);
        float nm = fmaxf(m, vv);
        float sc = __expf(m - nm);
        float p  = __expf(vv - nm);
        s  = fmaf(s, sc, p);
        am = fmaf(am, sc, p * we);
        m  = nm;
    }
    float g;
    if (lane < KIND) g = __fdividef(ai, cnt + 1e-5f);
    else             g = (s > 0.f) ? __fdividef(am, s) : 0.f;
    g_gath[(size_t)n * KTOT + lane] = g;
}

// ---------------- epilogue: out = relu(nodes@WS + gath@WG + bg) --------------
__global__ void __launch_bounds__(WARPS * 32)
epi_kernel(const float* __restrict__ nodes, const float* __restrict__ wgs,
           const float* __restrict__ wgg,   const float* __restrict__ bgg,
           float* __restrict__ out, int n_nodes) {
    __shared__ float4 sX[WARPS][8][8];
    __shared__ float4 sG[WARPS][8][8];

    int tid = threadIdx.x;
    int w = tid >> 5, lane = tid & 31;

    float ws[KTOT], wg[KTOT];
    #pragma unroll
    for (int j = 0; j < KTOT; j++) {
        ws[j] = __ldg(&wgs[j * KTOT + lane]);
        wg[j] = __ldg(&wgg[j * KTOT + lane]);
    }
    float bgk = __ldg(&bgg[lane]);

    int wid = blockIdx.x * WARPS + w;
    int n0 = wid * 8;
    if (n0 >= n_nodes) return;

    const float4* x4 = (const float4*)nodes;
    const float4* g4 = (const float4*)g_gath;
    int lim4 = n_nodes * 8;
    {
        int i1 = lane >> 3, j1 = lane & 7;
        int idxA = n0 * 8 + lane, idxB = idxA + 32;
        float4 z = make_float4(0.f, 0.f, 0.f, 0.f);
        sX[w][i1][j1]     = (idxA < lim4) ? __ldg(&x4[idxA]) : z;
        sX[w][i1 + 4][j1] = (idxB < lim4) ? __ldg(&x4[idxB]) : z;
        sG[w][i1][j1]     = (idxA < lim4) ? __ldg(&g4[idxA]) : z;
        sG[w][i1 + 4][j1] = (idxB < lim4) ? __ldg(&g4[idxB]) : z;
    }
    __syncwarp();

    #pragma unroll
    for (int i = 0; i < 8; i++) {
        int n = n0 + i;
        if (n >= n_nodes) break;
        float o = bgk;
        #pragma unroll
        for (int j4 = 0; j4 < 8; j4++) {
            float4 xv = sX[w][i][j4];
            float4 gv = sG[w][i][j4];
            o = fmaf(xv.x, ws[j4 * 4 + 0], o);
            o = fmaf(xv.y, ws[j4 * 4 + 1], o);
            o = fmaf(xv.z, ws[j4 * 4 + 2], o);
            o = fmaf(xv.w, ws[j4 * 4 + 3], o);
            o = fmaf(gv.x, wg[j4 * 4 + 0], o);
            o = fmaf(gv.y, wg[j4 * 4 + 1], o);
            o = fmaf(gv.z, wg[j4 * 4 + 2], o);
            o = fmaf(gv.w, wg[j4 * 4 + 3], o);
        }
        out[(size_t)n * KTOT + lane] = fmaxf(o, 0.f);
    }
}

// ---------------- launch ----------------
extern "C" void kernel_launch(void* const* d_in, const int* in_sizes, int n_in,
                              void* d_out, int out_size) {
    const float* nodes     = (const float*)d_in[0];
    const float* distance  = (const float*)d_in[1];
    const float* padding   = (const float*)d_in[2];
    const int*   receivers = (const int*)d_in[3];
    const int*   senders   = (const int*)d_in[4];
    const float* w1        = (const float*)d_in[5];
    const float* b1        = (const float*)d_in[6];
    const float* w2        = (const float*)d_in[7];
    const float* b2        = (const float*)d_in[8];
    const float* a         = (const float*)d_in[9];
    const float* b         = (const float*)d_in[10];
    const float* wgs       = (const float*)d_in[11];
    const float* wgg       = (const float*)d_in[12];
    const float* bgg       = (const float*)d_in[13];

    int n_nodes = in_sizes[0] / KTOT;
    int n_edges = in_sizes[1];

    int ethreads = (n_edges >> 2) + 1;
    int pwork = ethreads > n_nodes * 8 ? ethreads : n_nodes * 8;
    int pblocks = (pwork + 255) / 256;
    if (pblocks < 1) pblocks = 1;
    pre_kernel<<<pblocks, 256>>>(w1, b1, w2, b2, a, b, nodes,
                                 receivers, padding, n_edges, n_nodes);

    int gblocks = (n_nodes + GWARPS - 1) / GWARPS;
    gather_kernel<<<gblocks, GWARPS * 32>>>(nodes, distance, padding, senders, n_nodes);

    int nwarps = (n_nodes + 7) / 8;
    int eblocks = (nwarps + WARPS - 1) / WARPS;
    epi_kernel<<<eblocks, WARPS * 32>>>(nodes, wgs, wgg, bgg, (float*)d_out, n_nodes);
}